// round 12
// baseline (speedup 1.0000x reference)
#include <cuda_runtime.h>
#include <math.h>

#define Bq 4
#define Lq 2048
#define Hq 8
#define Dq 64
#define NSLOT 12                 // self + offsets 2^0 .. 2^10
#define SLAB4 (Hq * Dq / 4)      // 128 x 16B chunks per (b,l) slab

// exp(score) = ex2(dot * 0.125 * log2(e))
#define EXC 0.18033688011112042f

__device__ __forceinline__ float ex2f(float x) {
    float r;
    asm("ex2.approx.f32 %0, %1;" : "=f"(r) : "f"(x));
    return r;
}

// One warp handles TWO head-pair units of the same (b,l): bases base and
// base+32 (float4 units). The two units are fully independent instruction
// chains; interleaving them hides shfl/exp latency under the other unit's
// loads. lane ln owns 16B chunk ln of each 512B head-pair slab.
template <bool FULL>
__device__ __forceinline__ void run_pair(
    const float4* __restrict__ Q4, const float4* __restrict__ K4,
    const float4* __restrict__ V4, float4* __restrict__ O4,
    int base, int l, int hl)     // hl = lane & 15
{
    const float4 q0 = Q4[base];
    const float4 q1 = Q4[base + 32];

    // ---- phase 1: 24 front-batched K loads, per-lane partial dots ----
    float v0[16], v1[16];
#pragma unroll
    for (int t = 0; t < NSLOT; t++) {
        const int off = (t == 0) ? 0 : (1 << (t - 1));
        const bool ok = FULL || (off <= l);
        const int kb = base - (ok ? off * SLAB4 : 0);  // imm offset in FULL path
        const float4 ka = K4[kb];
        const float4 kc = K4[kb + 32];
        v0[t] = q0.x*ka.x + q0.y*ka.y + q0.z*ka.z + q0.w*ka.w;
        v1[t] = q1.x*kc.x + q1.y*kc.y + q1.z*kc.z + q1.w*kc.w;
    }
#pragma unroll
    for (int t = NSLOT; t < 16; t++) { v0[t] = 0.0f; v1[t] = 0.0f; }

    // ---- multi-value butterfly on both units (interleaved) ----
#pragma unroll
    for (int m = 8; m >= 1; m >>= 1) {
#pragma unroll
        for (int j = 0; j < m; j++) {
            const float s0 = (hl & m) ? v0[j] : v0[j + m];
            const float s1 = (hl & m) ? v1[j] : v1[j + m];
            const float o0 = __shfl_xor_sync(0xffffffffu, s0, m);
            const float o1 = __shfl_xor_sync(0xffffffffu, s1, m);
            v0[j] = ((hl & m) ? v0[j + m] : v0[j]) + o0;
            v1[j] = ((hl & m) ? v1[j + m] : v1[j]) + o1;
        }
    }

    // per-lane validity of slot hl
    bool okl;
    if (FULL) okl = (hl < NSLOT);
    else      okl = (hl == 0) || ((hl < NSLOT) && ((1 << (hl - 1)) <= l));

    const float e0 = okl ? ex2f(v0[0] * EXC) : 0.0f;
    const float e1 = okl ? ex2f(v1[0] * EXC) : 0.0f;

    float s0 = e0, s1 = e1;
    s0 += __shfl_xor_sync(0xffffffffu, s0, 1);
    s1 += __shfl_xor_sync(0xffffffffu, s1, 1);
    s0 += __shfl_xor_sync(0xffffffffu, s0, 2);
    s1 += __shfl_xor_sync(0xffffffffu, s1, 2);
    s0 += __shfl_xor_sync(0xffffffffu, s0, 4);
    s1 += __shfl_xor_sync(0xffffffffu, s1, 4);
    s0 += __shfl_xor_sync(0xffffffffu, s0, 8);
    s1 += __shfl_xor_sync(0xffffffffu, s1, 8);
    const float inv0 = 1.0f / s0;
    const float inv1 = 1.0f / s1;

    // ---- phase 2: V gathers + width-16 prob broadcast + accumulate ----
    float4 a0 = {0.f, 0.f, 0.f, 0.f};
    float4 a1 = {0.f, 0.f, 0.f, 0.f};
#pragma unroll
    for (int t = 0; t < NSLOT; t++) {
        const int off = (t == 0) ? 0 : (1 << (t - 1));
        const bool ok = FULL || (off <= l);
        const int vb = base - (ok ? off * SLAB4 : 0);
        const float4 va = V4[vb];
        const float4 vc = V4[vb + 32];
        const float p0 = __shfl_sync(0xffffffffu, e0, t, 16);
        const float p1 = __shfl_sync(0xffffffffu, e1, t, 16);
        a0.x += p0 * va.x; a0.y += p0 * va.y; a0.z += p0 * va.z; a0.w += p0 * va.w;
        a1.x += p1 * vc.x; a1.y += p1 * vc.y; a1.z += p1 * vc.z; a1.w += p1 * vc.w;
    }
    a0.x *= inv0; a0.y *= inv0; a0.z *= inv0; a0.w *= inv0;
    a1.x *= inv1; a1.y *= inv1; a1.z *= inv1; a1.w *= inv1;
    O4[base]      = a0;
    O4[base + 32] = a1;
}

__global__ __launch_bounds__(128) void logsparse_attn_kernel(
    const float4* __restrict__ Q4,
    const float4* __restrict__ K4,
    const float4* __restrict__ V4,
    float4* __restrict__ O4)
{
    const int wid  = (blockIdx.x * blockDim.x + threadIdx.x) >> 5;  // 0..16383
    const int lane = threadIdx.x & 31;
    const int gg = wid & 1;                      // which head-pair pair (0: g0/g1, 1: g2/g3)
    const int s = wid >> 1;                      // b*L + l
    const int l = s & (Lq - 1);

    const int base = s * SLAB4 + gg * 64 + lane; // 16B-chunk index of first unit
    const int hl = lane & 15;

    if (l >= 1024) {
        run_pair<true>(Q4, K4, V4, O4, base, l, hl);
    } else {
        run_pair<false>(Q4, K4, V4, O4, base, l, hl);
    }
}

extern "C" void kernel_launch(void* const* d_in, const int* in_sizes, int n_in,
                              void* d_out, int out_size)
{
    const float4* Q = (const float4*)d_in[0];
    const float4* K = (const float4*)d_in[1];
    const float4* V = (const float4*)d_in[2];
    float4* O = (float4*)d_out;

    const int total_warps = Bq * Lq * 2;             // 16384 (two units per warp)
    const int threads = 128;
    const int blocks = (total_warps * 32) / threads; // 4096
    logsparse_attn_kernel<<<blocks, threads>>>(Q, K, V, O);
}